// round 1
// baseline (speedup 1.0000x reference)
#include <cuda_runtime.h>
#include <cstdint>

// ---------------------------------------------------------------------------
// SymmetrizeRotavg:
//   scaled[n]   = inv_lat[b(n)]^T @ forces[n]
//   acc[symm_map[n,o]] += rot[o] @ scaled[n]   (o = 0..O-1)
//   out[n]      = lat[b(n)]^T @ (acc[n] / O)
//
// Scratch in __device__ globals (no allocations). acc padded to float4 so the
// scatter uses a single red.global.add.v4.f32 per (n,o) pair instead of three
// scalar atomics.
// ---------------------------------------------------------------------------

#define MAX_N (1 << 20)   // N = 1,048,576 for this problem
#define MAX_O 64

__device__ float4 g_scaled[MAX_N];
__device__ float4 g_acc[MAX_N];

// Stage 1: scaled = inv_lat^T f ; also zero the accumulator (must happen every
// launch so graph replays are deterministic).
__global__ __launch_bounds__(256) void k_prep(
    const float* __restrict__ inv_lat,
    const float* __restrict__ forces,
    int N, int A)
{
    int n = blockIdx.x * blockDim.x + threadIdx.x;
    if (n >= N) return;
    int b = n / A;
    float f0 = forces[3 * n + 0];
    float f1 = forces[3 * n + 1];
    float f2 = forces[3 * n + 2];
    const float* M = inv_lat + 9 * b;   // M[j*3+i]
    // scaled_i = sum_j M[j][i] * f_j
    float s0 = M[0] * f0 + M[3] * f1 + M[6] * f2;
    float s1 = M[1] * f0 + M[4] * f1 + M[7] * f2;
    float s2 = M[2] * f0 + M[5] * f1 + M[8] * f2;
    g_scaled[n] = make_float4(s0, s1, s2, 0.0f);
    g_acc[n]    = make_float4(0.0f, 0.0f, 0.0f, 0.0f);
}

__device__ __forceinline__ void red_add_v4(float4* p, float x, float y, float z)
{
    asm volatile(
        "{\n\t"
        ".reg .u64 ga;\n\t"
        "cvta.to.global.u64 ga, %0;\n\t"
        "red.global.add.v4.f32 [ga], {%1, %2, %3, %4};\n\t"
        "}"
        :: "l"(p), "f"(x), "f"(y), "f"(z), "f"(0.0f)
        : "memory");
}

// Stage 2: scatter-add. One thread handles one n and 4 consecutive ops
// (one int4 load from symm_map). Requires O % 4 == 0 (O = 48 here).
__global__ __launch_bounds__(256) void k_scatter4(
    const float* __restrict__ gops,   // (O,4,4)
    const int*   __restrict__ smap,   // (N,O)
    int N, int O)
{
    __shared__ float srot[MAX_O * 9];
    // Stage rot = gops[:, :3, :3] into shared, compacted to 9 floats per op.
    for (int t = threadIdx.x; t < O * 9; t += blockDim.x) {
        int o = t / 9;
        int e = t - o * 9;
        int i = e / 3;
        int j = e - i * 3;
        srot[t] = gops[o * 16 + i * 4 + j];
    }
    __syncthreads();

    int per_n = O >> 2;  // groups of 4 ops
    long long idx = (long long)blockIdx.x * blockDim.x + threadIdx.x;
    long long total = (long long)N * per_n;
    if (idx >= total) return;
    int n = (int)(idx / per_n);
    int k = (int)(idx - (long long)n * per_n);

    float4 s = g_scaled[n];
    // 128-bit coalesced load of 4 targets
    int4 t4 = *reinterpret_cast<const int4*>(smap + (long long)n * O + k * 4);
    int tgt[4] = { t4.x, t4.y, t4.z, t4.w };

#pragma unroll
    for (int r = 0; r < 4; r++) {
        int o = k * 4 + r;
        const float* R = srot + o * 9;   // R[i*3+j]
        // transformed_i = sum_j R[i][j] * s_j
        float x = R[0] * s.x + R[1] * s.y + R[2] * s.z;
        float y = R[3] * s.x + R[4] * s.y + R[5] * s.z;
        float z = R[6] * s.x + R[7] * s.y + R[8] * s.z;
        red_add_v4(&g_acc[tgt[r]], x, y, z);
    }
}

// Fallback (O not a multiple of 4): one thread per (n,o).
__global__ __launch_bounds__(256) void k_scatter1(
    const float* __restrict__ gops,
    const int*   __restrict__ smap,
    int N, int O)
{
    __shared__ float srot[MAX_O * 9];
    for (int t = threadIdx.x; t < O * 9; t += blockDim.x) {
        int o = t / 9;
        int e = t - o * 9;
        int i = e / 3;
        int j = e - i * 3;
        srot[t] = gops[o * 16 + i * 4 + j];
    }
    __syncthreads();

    long long idx = (long long)blockIdx.x * blockDim.x + threadIdx.x;
    long long total = (long long)N * O;
    if (idx >= total) return;
    int n = (int)(idx / O);
    int o = (int)(idx - (long long)n * O);

    float4 s = g_scaled[n];
    int tgt = smap[(long long)n * O + o];
    const float* R = srot + o * 9;
    float x = R[0] * s.x + R[1] * s.y + R[2] * s.z;
    float y = R[3] * s.x + R[4] * s.y + R[5] * s.z;
    float z = R[6] * s.x + R[7] * s.y + R[8] * s.z;
    red_add_v4(&g_acc[tgt], x, y, z);
}

// Stage 3: out = lat^T (acc / O)
__global__ __launch_bounds__(256) void k_final(
    const float* __restrict__ lat,
    float* __restrict__ out,
    int N, int A, float inv_count)
{
    int n = blockIdx.x * blockDim.x + threadIdx.x;
    if (n >= N) return;
    int b = n / A;
    float4 a = g_acc[n];
    float s0 = a.x * inv_count;
    float s1 = a.y * inv_count;
    float s2 = a.z * inv_count;
    const float* L = lat + 9 * b;   // L[j*3+i]
    out[3 * n + 0] = L[0] * s0 + L[3] * s1 + L[6] * s2;
    out[3 * n + 1] = L[1] * s0 + L[4] * s1 + L[7] * s2;
    out[3 * n + 2] = L[2] * s0 + L[5] * s1 + L[8] * s2;
}

extern "C" void kernel_launch(void* const* d_in, const int* in_sizes, int n_in,
                              void* d_out, int out_size)
{
    const float* lattices     = (const float*)d_in[0];  // (B,3,3)
    const float* inv_lattices = (const float*)d_in[1];  // (B,3,3)
    const float* forces       = (const float*)d_in[2];  // (N,3)
    // d_in[3] = num_atoms (int64, uniform A)
    const float* general_ops  = (const float*)d_in[4];  // (O,4,4)
    const int*   symm_map     = (const int*)d_in[5];    // (N,O)
    // d_in[6] = num_general_ops (int64, uniform O)

    int B = in_sizes[0] / 9;
    int N = in_sizes[2] / 3;
    int O = in_sizes[4] / 16;
    int A = N / B;

    float* out = (float*)d_out;

    const int TPB = 256;
    int blocks_n = (N + TPB - 1) / TPB;

    k_prep<<<blocks_n, TPB>>>(inv_lattices, forces, N, A);

    if ((O & 3) == 0) {
        long long total = (long long)N * (O >> 2);
        int blocks = (int)((total + TPB - 1) / TPB);
        k_scatter4<<<blocks, TPB>>>(general_ops, symm_map, N, O);
    } else {
        long long total = (long long)N * O;
        int blocks = (int)((total + TPB - 1) / TPB);
        k_scatter1<<<blocks, TPB>>>(general_ops, symm_map, N, O);
    }

    k_final<<<blocks_n, TPB>>>(lattices, out, N, A, 1.0f / (float)O);
}